// round 10
// baseline (speedup 1.0000x reference)
#include <cuda_runtime.h>
#include <cstdint>

// PointNetSaModule via mma.sync bf16-split (HMMA, plain sm_103-compatible).
// Per CTA: 128 rows; warp = one 16-row group (M=16). Layers 67->64->64->128
// (BN folded), ReLU, max over the 16 rows. D = Ah@Wh + Ah@Wl + Al@Wh in f32.
// smem tiles store bf16x2 kpairs interleaved (c, c+4) so every A/B fragment
// is one conflict-free LDS.64 at stride 40 u32.

typedef uint32_t u32;
typedef uint64_t u64;

#define NS_SZ  16384
#define HW_SZ  65536
#define OUT_ONE (4 * 16384 * 128)
#define THREADS 256

// u32 offsets in dynamic smem
#define OFF_T0    0
#define OFF_T1    64
#define OFF_T2    128
#define OFF_S0    256
#define OFF_S1    320
#define OFF_S2    384
#define OFF_AH    512        // 128 rows x 40 u32
#define OFF_AL    5632
#define OFF_W0H   10752      // 64 x 40
#define OFF_W0L   13312
#define OFF_W1H   15872
#define OFF_W1L   18432
#define OFF_W2H   20992      // 128 x 40
#define OFF_W2L   26112
#define OFF_STAGE 31232      // 8 warps x 128 f32
#define SMEM_U32  32256
#define SMEM_BYTES (SMEM_U32 * 4)

// physical slot of logical kpair p (interleave (c,c+4) adjacent within ktile)
__device__ __host__ __forceinline__ int POS(int p) {
    int q = p & 7;
    return (p & ~7) + ((q < 4) ? 2 * q : 2 * (q - 4) + 1);
}

__device__ __forceinline__ u32 cvt2(float lo, float hi) {   // lower half = lo
    u32 r; asm("cvt.rn.bf16x2.f32 %0, %1, %2;" : "=r"(r) : "f"(hi), "f"(lo)); return r;
}
__device__ __forceinline__ void split2(float y0, float y1, u32& h, u32& l) {
    h = cvt2(y0, y1);
    float h0 = __uint_as_float(h << 16);
    float h1 = __uint_as_float(h & 0xFFFF0000u);
    l = cvt2(y0 - h0, y1 - h1);
}
__device__ __forceinline__ void mma_bf16(float* d, u32 a0, u32 a1, u32 a2, u32 a3,
                                         u32 b0, u32 b1) {
    asm("mma.sync.aligned.m16n8k16.row.col.f32.bf16.bf16.f32 "
        "{%0,%1,%2,%3}, {%4,%5,%6,%7}, {%8,%9}, {%0,%1,%2,%3};"
        : "+f"(d[0]), "+f"(d[1]), "+f"(d[2]), "+f"(d[3])
        : "r"(a0), "r"(a1), "r"(a2), "r"(a3), "r"(b0), "r"(b1));
}
__device__ __forceinline__ u32 lo32(u64 v) { return (u32)v; }
__device__ __forceinline__ u32 hi32(u64 v) { return (u32)(v >> 32); }

// Load A fragments (hi & lo arrays) for NKT ktiles. a[kt][0..3]: PTX m16n8k16 A map.
template<int NKT>
__device__ __forceinline__ void load_afrags(u32 ah[][4], u32 al[][4],
        const u64* AHu, const u64* ALu, int rowA, int c)
{
    #pragma unroll
    for (int kt = 0; kt < NKT; kt++) {
        u64 v0 = AHu[rowA * 20 + kt * 4 + c];
        u64 v1 = AHu[(rowA + 8) * 20 + kt * 4 + c];
        ah[kt][0] = lo32(v0); ah[kt][2] = hi32(v0);
        ah[kt][1] = lo32(v1); ah[kt][3] = hi32(v1);
        u64 w0v = ALu[rowA * 20 + kt * 4 + c];
        u64 w1v = ALu[(rowA + 8) * 20 + kt * 4 + c];
        al[kt][0] = lo32(w0v); al[kt][2] = hi32(w0v);
        al[kt][1] = lo32(w1v); al[kt][3] = hi32(w1v);
    }
}

// bias+ReLU+split writeback for NJ=8 ntiles (64 channels) into act arrays
__device__ __forceinline__ void epi_store(float d[][4], u64* AHu, u64* ALu,
        const float* T, int rowA, int c)
{
    #pragma unroll
    for (int t = 0; t < 4; t++) {
        float2 tA = *(const float2*)(T + 16 * t + 2 * c);
        float2 tB = *(const float2*)(T + 16 * t + 8 + 2 * c);
        // rows r (regs 0,1)
        {
            float y00 = fmaxf(d[2*t][0]   + tA.x, 0.f), y01 = fmaxf(d[2*t][1]   + tA.y, 0.f);
            float y10 = fmaxf(d[2*t+1][0] + tB.x, 0.f), y11 = fmaxf(d[2*t+1][1] + tB.y, 0.f);
            u32 hA, lA, hB, lB;
            split2(y00, y01, hA, lA); split2(y10, y11, hB, lB);
            AHu[rowA * 20 + 4 * t + c] = (u64)hA | ((u64)hB << 32);
            ALu[rowA * 20 + 4 * t + c] = (u64)lA | ((u64)lB << 32);
        }
        // rows r+8 (regs 2,3)
        {
            float y00 = fmaxf(d[2*t][2]   + tA.x, 0.f), y01 = fmaxf(d[2*t][3]   + tA.y, 0.f);
            float y10 = fmaxf(d[2*t+1][2] + tB.x, 0.f), y11 = fmaxf(d[2*t+1][3] + tB.y, 0.f);
            u32 hA, lA, hB, lB;
            split2(y00, y01, hA, lA); split2(y10, y11, hB, lB);
            AHu[(rowA + 8) * 20 + 4 * t + c] = (u64)hA | ((u64)hB << 32);
            ALu[(rowA + 8) * 20 + 4 * t + c] = (u64)lA | ((u64)lB << 32);
        }
    }
}

__global__ void __launch_bounds__(THREADS, 1)
pointnet_sa_hmma_kernel(
    const float* __restrict__ xyz, const float* __restrict__ pts,
    const float* __restrict__ xyzs, const int* __restrict__ nbr,
    const float* __restrict__ vmask,
    const float* __restrict__ w0, const float* __restrict__ b0,
    const float* __restrict__ g0, const float* __restrict__ be0,
    const float* __restrict__ m0, const float* __restrict__ v0,
    const float* __restrict__ w1, const float* __restrict__ b1,
    const float* __restrict__ g1, const float* __restrict__ be1,
    const float* __restrict__ m1, const float* __restrict__ v1,
    const float* __restrict__ w2, const float* __restrict__ b2,
    const float* __restrict__ g2, const float* __restrict__ be2,
    const float* __restrict__ m2, const float* __restrict__ v2,
    float* __restrict__ out, int copies)
{
    extern __shared__ u32 smu[];
    float* smf = (float*)smu;
    const int tid = threadIdx.x;

    // ---- phase 1: BN fold scales + biases ----
    if (tid < 64) {
        float s = g0[tid] * rsqrtf(v0[tid] + 1e-5f);
        smf[OFF_S0 + tid] = s;
        smf[OFF_T0 + tid] = (b0[tid] - m0[tid]) * s + be0[tid];
        float s1 = g1[tid] * rsqrtf(v1[tid] + 1e-5f);
        smf[OFF_S1 + tid] = s1;
        smf[OFF_T1 + tid] = (b1[tid] - m1[tid]) * s1 + be1[tid];
    }
    if (tid < 128) {
        float s = g2[tid] * rsqrtf(v2[tid] + 1e-5f);
        smf[OFF_S2 + tid] = s;
        smf[OFF_T2 + tid] = (b2[tid] - m2[tid]) * s + be2[tid];
    }
    __syncthreads();

    // ---- phase 2: weight tiles (hi/lo split, [n][kpair phys], stride 40) ----
    for (int i = tid; i < 64 * 40; i += THREADS) {
        int n = i / 40, pos = i % 40;
        int q = pos & 7;
        int p = (pos & ~7) + ((q & 1) ? (q >> 1) + 4 : (q >> 1));
        int k0 = 2 * p, k1 = k0 + 1;
        float s = smf[OFF_S0 + n];
        float a = 0.f, b = 0.f;
        if (k0 < 67) { int sr = (k0 < 64) ? k0 + 3 : k0 - 64; a = w0[sr * 64 + n] * s; }
        if (k1 < 67) { int sr = (k1 < 64) ? k1 + 3 : k1 - 64; b = w0[sr * 64 + n] * s; }
        u32 h, l; split2(a, b, h, l);
        smu[OFF_W0H + i] = h; smu[OFF_W0L + i] = l;
    }
    for (int i = tid; i < 64 * 40; i += THREADS) {
        int n = i / 40, pos = i % 40;
        int q = pos & 7;
        int p = (pos & ~7) + ((q & 1) ? (q >> 1) + 4 : (q >> 1));
        int k0 = 2 * p;
        float s = smf[OFF_S1 + n];
        float a = (k0 < 64)     ? w1[k0 * 64 + n] * s       : 0.f;
        float b = (k0 + 1 < 64) ? w1[(k0 + 1) * 64 + n] * s : 0.f;
        u32 h, l; split2(a, b, h, l);
        smu[OFF_W1H + i] = h; smu[OFF_W1L + i] = l;
    }
    for (int i = tid; i < 128 * 40; i += THREADS) {
        int n = i / 40, pos = i % 40;
        int q = pos & 7;
        int p = (pos & ~7) + ((q & 1) ? (q >> 1) + 4 : (q >> 1));
        int k0 = 2 * p;
        float s = smf[OFF_S2 + n];
        float a = (k0 < 64)     ? w2[k0 * 128 + n] * s       : 0.f;
        float b = (k0 + 1 < 64) ? w2[(k0 + 1) * 128 + n] * s : 0.f;
        u32 h, l; split2(a, b, h, l);
        smu[OFF_W2H + i] = h; smu[OFF_W2L + i] = l;
    }
    // zero act tail slots (pos 32..39)
    for (int i = tid; i < 128 * 8; i += THREADS) {
        int rr = i >> 3, pp = 32 + (i & 7);
        smu[OFF_AH + rr * 40 + pp] = 0;
        smu[OFF_AL + rr * 40 + pp] = 0;
    }
    __syncthreads();

    // ---- phase 3: gather (warp-local rows) ----
    {
        const int r = tid >> 1, h = tid & 1;   // 2 threads per row
        const int grp = blockIdx.x * 8 + (r >> 4);
        const int b = grp >> 14, n = grp & (NS_SZ - 1);
        const int e = grp * 16 + (r & 15);
        const int idx = nbr[e];
        const float mk = vmask[e];
        const float4* pp = (const float4*)(pts + (size_t)(b * HW_SZ + idx) * 64) + h * 8;
        #pragma unroll
        for (int i = 0; i < 8; i++) {
            float4 v = pp[i];
            v.x *= mk; v.y *= mk; v.z *= mk; v.w *= mk;
            int p0 = h * 16 + 2 * i;
            u32 hh, ll;
            split2(v.x, v.y, hh, ll);
            smu[OFF_AH + r * 40 + POS(p0)] = hh;  smu[OFF_AL + r * 40 + POS(p0)] = ll;
            split2(v.z, v.w, hh, ll);
            smu[OFF_AH + r * 40 + POS(p0 + 1)] = hh;  smu[OFF_AL + r * 40 + POS(p0 + 1)] = ll;
        }
        if (h == 1) {
            const float* cp = xyzs + (size_t)(b * NS_SZ + n) * 3;
            const float* gx = xyz + (size_t)(b * HW_SZ + idx) * 3;
            float d0 = gx[0] * mk - cp[0];
            float d1 = gx[1] * mk - cp[1];
            float d2 = gx[2] * mk - cp[2];
            u32 hh, ll;
            split2(d0, d1, hh, ll);
            smu[OFF_AH + r * 40 + POS(32)] = hh;  smu[OFF_AL + r * 40 + POS(32)] = ll;
            split2(d2, 0.f, hh, ll);
            smu[OFF_AH + r * 40 + POS(33)] = hh;  smu[OFF_AL + r * 40 + POS(33)] = ll;
        }
    }
    __syncwarp();

    const int lane = tid & 31;
    const int warp = tid >> 5;
    const int r = lane >> 2;        // groupID
    const int c = lane & 3;         // threadID in group
    const int rowA = warp * 16 + r;

    u64* AHu = (u64*)(smu + OFF_AH);
    u64* ALu = (u64*)(smu + OFF_AL);
    const u64* W0Hu = (const u64*)(smu + OFF_W0H);
    const u64* W0Lu = (const u64*)(smu + OFF_W0L);
    const u64* W1Hu = (const u64*)(smu + OFF_W1H);
    const u64* W1Lu = (const u64*)(smu + OFF_W1L);
    const u64* W2Hu = (const u64*)(smu + OFF_W2H);
    const u64* W2Lu = (const u64*)(smu + OFF_W2L);

    // ===== layer 0: K=80 (5 ktiles), N=64 =====
    {
        u32 ah[5][4], al[5][4];
        load_afrags<5>(ah, al, AHu, ALu, rowA, c);
        float d[8][4];
        #pragma unroll
        for (int j = 0; j < 8; j++) { d[j][0]=0.f; d[j][1]=0.f; d[j][2]=0.f; d[j][3]=0.f; }
        #pragma unroll
        for (int kt = 0; kt < 5; kt++) {
            #pragma unroll
            for (int j = 0; j < 8; j++) {
                int bi = (8 * j + r) * 20 + kt * 4 + c;
                u64 bh = W0Hu[bi], bl = W0Lu[bi];
                mma_bf16(d[j], ah[kt][0], ah[kt][1], ah[kt][2], ah[kt][3], lo32(bh), hi32(bh));
                mma_bf16(d[j], ah[kt][0], ah[kt][1], ah[kt][2], ah[kt][3], lo32(bl), hi32(bl));
                mma_bf16(d[j], al[kt][0], al[kt][1], al[kt][2], al[kt][3], lo32(bh), hi32(bh));
            }
        }
        __syncwarp();
        epi_store(d, AHu, ALu, smf + OFF_T0, rowA, c);
        __syncwarp();
    }

    // ===== layer 1: K=64 (4 ktiles), N=64 =====
    {
        u32 ah[4][4], al[4][4];
        load_afrags<4>(ah, al, AHu, ALu, rowA, c);
        float d[8][4];
        #pragma unroll
        for (int j = 0; j < 8; j++) { d[j][0]=0.f; d[j][1]=0.f; d[j][2]=0.f; d[j][3]=0.f; }
        #pragma unroll
        for (int kt = 0; kt < 4; kt++) {
            #pragma unroll
            for (int j = 0; j < 8; j++) {
                int bi = (8 * j + r) * 20 + kt * 4 + c;
                u64 bh = W1Hu[bi], bl = W1Lu[bi];
                mma_bf16(d[j], ah[kt][0], ah[kt][1], ah[kt][2], ah[kt][3], lo32(bh), hi32(bh));
                mma_bf16(d[j], ah[kt][0], ah[kt][1], ah[kt][2], ah[kt][3], lo32(bl), hi32(bl));
                mma_bf16(d[j], al[kt][0], al[kt][1], al[kt][2], al[kt][3], lo32(bh), hi32(bh));
            }
        }
        __syncwarp();
        epi_store(d, AHu, ALu, smf + OFF_T1, rowA, c);
        __syncwarp();
    }

    // ===== layer 2: K=64, N=128; max over 16 rows; store =====
    {
        u32 ah[4][4], al[4][4];
        load_afrags<4>(ah, al, AHu, ALu, rowA, c);
        float d[16][4];
        #pragma unroll
        for (int j = 0; j < 16; j++) { d[j][0]=0.f; d[j][1]=0.f; d[j][2]=0.f; d[j][3]=0.f; }
        #pragma unroll
        for (int kt = 0; kt < 4; kt++) {
            #pragma unroll
            for (int j = 0; j < 16; j++) {
                int bi = (8 * j + r) * 20 + kt * 4 + c;
                u64 bh = W2Hu[bi], bl = W2Lu[bi];
                mma_bf16(d[j], ah[kt][0], ah[kt][1], ah[kt][2], ah[kt][3], lo32(bh), hi32(bh));
                mma_bf16(d[j], ah[kt][0], ah[kt][1], ah[kt][2], ah[kt][3], lo32(bl), hi32(bl));
                mma_bf16(d[j], al[kt][0], al[kt][1], al[kt][2], al[kt][3], lo32(bh), hi32(bh));
            }
        }
        // thread-local max (rows r, r+8), then reduce over r via xor 4,8,16
        float mx0[16], mx1[16];
        #pragma unroll
        for (int j = 0; j < 16; j++) {
            mx0[j] = fmaxf(d[j][0], d[j][2]);
            mx1[j] = fmaxf(d[j][1], d[j][3]);
        }
        #pragma unroll
        for (int off = 4; off <= 16; off <<= 1) {
            #pragma unroll
            for (int j = 0; j < 16; j++) {
                mx0[j] = fmaxf(mx0[j], __shfl_xor_sync(0xffffffffu, mx0[j], off));
                mx1[j] = fmaxf(mx1[j], __shfl_xor_sync(0xffffffffu, mx1[j], off));
            }
        }
        float* stage = smf + OFF_STAGE + warp * 128;
        if (lane < 4) {
            #pragma unroll
            for (int j = 0; j < 16; j++) {
                float2 tv = *(const float2*)(smf + OFF_T2 + 8 * j + 2 * c);
                float2 o;
                o.x = fmaxf(mx0[j] + tv.x, 0.f);
                o.y = fmaxf(mx1[j] + tv.y, 0.f);
                *(float2*)(stage + 8 * j + 2 * c) = o;
            }
        }
        __syncwarp();
        float4 o = ((const float4*)stage)[lane];
        const int grp = blockIdx.x * 8 + warp;
        const long ofs = (long)grp * 128 + 4 * lane;
        *(float4*)(out + ofs) = o;
        if (copies > 1) *(float4*)(out + OUT_ONE + ofs) = o;
    }
}

extern "C" void kernel_launch(void* const* d_in, const int* in_sizes, int n_in,
                              void* d_out, int out_size)
{
    const float* xyz   = (const float*)d_in[0];
    const float* pts   = (const float*)d_in[1];
    const float* xyzs  = (const float*)d_in[2];
    const int*   nbr   = (const int*)  d_in[3];
    const float* vmask = (const float*)d_in[4];
    const float* w0  = (const float*)d_in[5];
    const float* b0  = (const float*)d_in[6];
    const float* g0  = (const float*)d_in[7];
    const float* be0 = (const float*)d_in[8];
    const float* m0  = (const float*)d_in[9];
    const float* v0  = (const float*)d_in[10];
    const float* w1  = (const float*)d_in[11];
    const float* b1  = (const float*)d_in[12];
    const float* g1  = (const float*)d_in[13];
    const float* be1 = (const float*)d_in[14];
    const float* m1  = (const float*)d_in[15];
    const float* v1  = (const float*)d_in[16];
    const float* w2  = (const float*)d_in[17];
    const float* b2  = (const float*)d_in[18];
    const float* g2  = (const float*)d_in[19];
    const float* be2 = (const float*)d_in[20];
    const float* m2  = (const float*)d_in[21];
    const float* v2  = (const float*)d_in[22];

    int copies = (out_size >= 2 * OUT_ONE) ? 2 : 1;

    cudaFuncSetAttribute(pointnet_sa_hmma_kernel,
                         cudaFuncAttributeMaxDynamicSharedMemorySize, SMEM_BYTES);

    const int blocks = (4 * NS_SZ) / 8;   // 8192 CTAs x 128 rows
    pointnet_sa_hmma_kernel<<<blocks, THREADS, SMEM_BYTES>>>(
        xyz, pts, xyzs, nbr, vmask,
        w0, b0, g0, be0, m0, v0,
        w1, b1, g1, be1, m1, v1,
        w2, b2, g2, be2, m2, v2,
        (float*)d_out, copies);
}

// round 11
// speedup vs baseline: 1.6195x; 1.6195x over previous
#include <cuda_runtime.h>
#include <cuda_fp16.h>
#include <cstdint>

// PointNetSaModule via mma.sync fp16 2-term split (sm_103-safe HMMA).
// A = ah + al (fp16 split, ~2^-22); W = single fp16 (2^-12). D = ah@W + al@W in f32.
// Per CTA: 256 rows (16 groups); warp = 32 rows (2 groups, M=32 amortizes B loads).
// Layers 67->64->64->128 (BN folded), ReLU, max over each 16-row group.

typedef uint32_t u32;
typedef uint64_t u64;

#define NS_SZ  16384
#define HW_SZ  65536
#define OUT_ONE (4 * 16384 * 128)
#define THREADS 256

// u32 offsets in dynamic smem
#define OFF_T0    0
#define OFF_T1    64
#define OFF_T2    128
#define OFF_S0    256
#define OFF_S1    320
#define OFF_S2    384
#define OFF_AH    512                    // 256 rows x 40 u32
#define OFF_AL    (OFF_AH + 256 * 40)    // 10752
#define OFF_W0    (OFF_AL + 256 * 40)    // 20992  (64 x 40)
#define OFF_W1    (OFF_W0 + 64 * 40)     // 23552
#define OFF_W2    (OFF_W1 + 64 * 40)     // 26112  (128 x 40)
#define OFF_STAGE (OFF_W2 + 128 * 40)    // 31232  (8 warps x 256 f32)
#define SMEM_U32  (OFF_STAGE + 8 * 256)  // 33280
#define SMEM_BYTES (SMEM_U32 * 4)        // 133120

// physical slot of logical kpair p (interleave (c, c+4) adjacent within ktile)
__device__ __forceinline__ int POS(int p) {
    int q = p & 7;
    return (p & ~7) + ((q < 4) ? 2 * q : 2 * (q - 4) + 1);
}

__device__ __forceinline__ u32 packh2(float lo, float hi) {   // low half = lo
    __half2 h = __floats2half2_rn(lo, hi);
    return *(u32*)&h;
}
__device__ __forceinline__ void split2h(float y0, float y1, u32& h, u32& l) {
    h = packh2(y0, y1);
    __half2 hh = *(__half2*)&h;
    float2 f = __half22float2(hh);
    l = packh2(y0 - f.x, y1 - f.y);
}
__device__ __forceinline__ void mma_f16(float* d, u32 a0, u32 a1, u32 a2, u32 a3,
                                        u32 b0, u32 b1) {
    asm("mma.sync.aligned.m16n8k16.row.col.f32.f16.f16.f32 "
        "{%0,%1,%2,%3}, {%4,%5,%6,%7}, {%8,%9}, {%0,%1,%2,%3};"
        : "+f"(d[0]), "+f"(d[1]), "+f"(d[2]), "+f"(d[3])
        : "r"(a0), "r"(a1), "r"(a2), "r"(a3), "r"(b0), "r"(b1));
}
__device__ __forceinline__ u32 lo32(u64 v) { return (u32)v; }
__device__ __forceinline__ u32 hi32(u64 v) { return (u32)(v >> 32); }

// Load one ktile's A fragments (hi & lo) for m-tile at rowA.
__device__ __forceinline__ void load_afrag(u32 ah[4], u32 al[4],
        const u64* AHu, const u64* ALu, int rowA, int kt, int c)
{
    u64 v0 = AHu[rowA * 20 + kt * 4 + c];
    u64 v1 = AHu[(rowA + 8) * 20 + kt * 4 + c];
    ah[0] = lo32(v0); ah[2] = hi32(v0);
    ah[1] = lo32(v1); ah[3] = hi32(v1);
    u64 w0 = ALu[rowA * 20 + kt * 4 + c];
    u64 w1 = ALu[(rowA + 8) * 20 + kt * 4 + c];
    al[0] = lo32(w0); al[2] = hi32(w0);
    al[1] = lo32(w1); al[3] = hi32(w1);
}

// bias+ReLU+fp16-split writeback of 64 channels into act arrays (one m-tile)
__device__ __forceinline__ void epi_store(float d[][4], u64* AHu, u64* ALu,
        const float* T, int rowA, int c)
{
    #pragma unroll
    for (int t = 0; t < 4; t++) {
        float2 tA = *(const float2*)(T + 16 * t + 2 * c);
        float2 tB = *(const float2*)(T + 16 * t + 8 + 2 * c);
        {
            float y00 = fmaxf(d[2*t][0]   + tA.x, 0.f), y01 = fmaxf(d[2*t][1]   + tA.y, 0.f);
            float y10 = fmaxf(d[2*t+1][0] + tB.x, 0.f), y11 = fmaxf(d[2*t+1][1] + tB.y, 0.f);
            u32 hA, lA, hB, lB;
            split2h(y00, y01, hA, lA); split2h(y10, y11, hB, lB);
            AHu[rowA * 20 + 4 * t + c] = (u64)hA | ((u64)hB << 32);
            ALu[rowA * 20 + 4 * t + c] = (u64)lA | ((u64)lB << 32);
        }
        {
            float y00 = fmaxf(d[2*t][2]   + tA.x, 0.f), y01 = fmaxf(d[2*t][3]   + tA.y, 0.f);
            float y10 = fmaxf(d[2*t+1][2] + tB.x, 0.f), y11 = fmaxf(d[2*t+1][3] + tB.y, 0.f);
            u32 hA, lA, hB, lB;
            split2h(y00, y01, hA, lA); split2h(y10, y11, hB, lB);
            AHu[(rowA + 8) * 20 + 4 * t + c] = (u64)hA | ((u64)hB << 32);
            ALu[(rowA + 8) * 20 + 4 * t + c] = (u64)lA | ((u64)lB << 32);
        }
    }
}

// One N=64 layer for a warp's 32 rows (2 m-tiles), in-place act update.
template<int NKT>
__device__ __forceinline__ void layer_n64(u64* AHu, u64* ALu, const u64* Wu,
        const float* T, int base, int r, int c)
{
    float d[2][8][4];
    #pragma unroll
    for (int m = 0; m < 2; m++)
        #pragma unroll
        for (int j = 0; j < 8; j++)
            { d[m][j][0]=0.f; d[m][j][1]=0.f; d[m][j][2]=0.f; d[m][j][3]=0.f; }
    #pragma unroll
    for (int kt = 0; kt < NKT; kt++) {
        u32 ah[2][4], al[2][4];
        load_afrag(ah[0], al[0], AHu, ALu, base + r,      kt, c);
        load_afrag(ah[1], al[1], AHu, ALu, base + 16 + r, kt, c);
        #pragma unroll
        for (int j = 0; j < 8; j++) {
            u64 b = Wu[(8 * j + r) * 20 + kt * 4 + c];
            u32 b0 = lo32(b), b1 = hi32(b);
            #pragma unroll
            for (int m = 0; m < 2; m++) {
                mma_f16(d[m][j], ah[m][0], ah[m][1], ah[m][2], ah[m][3], b0, b1);
                mma_f16(d[m][j], al[m][0], al[m][1], al[m][2], al[m][3], b0, b1);
            }
        }
    }
    __syncwarp();
    epi_store(d[0], AHu, ALu, T, base + r,      c);
    epi_store(d[1], AHu, ALu, T, base + 16 + r, c);
    __syncwarp();
}

__global__ void __launch_bounds__(THREADS, 1)
pointnet_sa_hmma2_kernel(
    const float* __restrict__ xyz, const float* __restrict__ pts,
    const float* __restrict__ xyzs, const int* __restrict__ nbr,
    const float* __restrict__ vmask,
    const float* __restrict__ w0, const float* __restrict__ b0,
    const float* __restrict__ g0, const float* __restrict__ be0,
    const float* __restrict__ m0, const float* __restrict__ v0,
    const float* __restrict__ w1, const float* __restrict__ b1,
    const float* __restrict__ g1, const float* __restrict__ be1,
    const float* __restrict__ m1, const float* __restrict__ v1,
    const float* __restrict__ w2, const float* __restrict__ b2,
    const float* __restrict__ g2, const float* __restrict__ be2,
    const float* __restrict__ m2, const float* __restrict__ v2,
    float* __restrict__ out, int copies)
{
    extern __shared__ u32 smu[];
    float* smf = (float*)smu;
    const int tid = threadIdx.x;

    // ---- BN fold scales + biases ----
    if (tid < 64) {
        float s = g0[tid] * rsqrtf(v0[tid] + 1e-5f);
        smf[OFF_S0 + tid] = s;
        smf[OFF_T0 + tid] = (b0[tid] - m0[tid]) * s + be0[tid];
        float s1 = g1[tid] * rsqrtf(v1[tid] + 1e-5f);
        smf[OFF_S1 + tid] = s1;
        smf[OFF_T1 + tid] = (b1[tid] - m1[tid]) * s1 + be1[tid];
    }
    if (tid < 128) {
        float s = g2[tid] * rsqrtf(v2[tid] + 1e-5f);
        smf[OFF_S2 + tid] = s;
        smf[OFF_T2 + tid] = (b2[tid] - m2[tid]) * s + be2[tid];
    }
    __syncthreads();

    // ---- weight tiles (single fp16, [n][kpair phys], stride 40) ----
    for (int i = tid; i < 64 * 40; i += THREADS) {
        int n = i / 40, pos = i % 40;
        int q = pos & 7;
        int p = (pos & ~7) + ((q & 1) ? (q >> 1) + 4 : (q >> 1));
        int k0 = 2 * p, k1 = k0 + 1;
        float s = smf[OFF_S0 + n];
        float a = 0.f, b = 0.f;
        if (k0 < 67) { int sr = (k0 < 64) ? k0 + 3 : k0 - 64; a = w0[sr * 64 + n] * s; }
        if (k1 < 67) { int sr = (k1 < 64) ? k1 + 3 : k1 - 64; b = w0[sr * 64 + n] * s; }
        smu[OFF_W0 + i] = packh2(a, b);
    }
    for (int i = tid; i < 64 * 40; i += THREADS) {
        int n = i / 40, pos = i % 40;
        int q = pos & 7;
        int p = (pos & ~7) + ((q & 1) ? (q >> 1) + 4 : (q >> 1));
        int k0 = 2 * p;
        float s = smf[OFF_S1 + n];
        float a = (k0 < 64)     ? w1[k0 * 64 + n] * s       : 0.f;
        float b = (k0 + 1 < 64) ? w1[(k0 + 1) * 64 + n] * s : 0.f;
        smu[OFF_W1 + i] = packh2(a, b);
    }
    for (int i = tid; i < 128 * 40; i += THREADS) {
        int n = i / 40, pos = i % 40;
        int q = pos & 7;
        int p = (pos & ~7) + ((q & 1) ? (q >> 1) + 4 : (q >> 1));
        int k0 = 2 * p;
        float s = smf[OFF_S2 + n];
        float a = (k0 < 64)     ? w2[k0 * 128 + n] * s       : 0.f;
        float b = (k0 + 1 < 64) ? w2[(k0 + 1) * 128 + n] * s : 0.f;
        smu[OFF_W2 + i] = packh2(a, b);
    }

    // ---- gather: thread owns row = tid (256 rows/CTA) ----
    {
        const int r = tid;
        const int grp = blockIdx.x * 16 + (r >> 4);
        const int b = grp >> 14, n = grp & (NS_SZ - 1);
        const int e = grp * 16 + (r & 15);
        const int idx = nbr[e];
        const float mk = vmask[e];
        const float4* pp = (const float4*)(pts + (size_t)(b * HW_SZ + idx) * 64);
        u32* AH = smu + OFF_AH + r * 40;
        u32* AL = smu + OFF_AL + r * 40;
        #pragma unroll
        for (int i = 0; i < 16; i++) {
            float4 v = pp[i];
            v.x *= mk; v.y *= mk; v.z *= mk; v.w *= mk;
            u32 hh, ll;
            split2h(v.x, v.y, hh, ll);
            AH[POS(2 * i)] = hh;  AL[POS(2 * i)] = ll;
            split2h(v.z, v.w, hh, ll);
            AH[POS(2 * i + 1)] = hh;  AL[POS(2 * i + 1)] = ll;
        }
        const float* cp = xyzs + (size_t)(b * NS_SZ + n) * 3;
        const float* gx = xyz + (size_t)(b * HW_SZ + idx) * 3;
        float d0 = gx[0] * mk - cp[0];
        float d1 = gx[1] * mk - cp[1];
        float d2 = gx[2] * mk - cp[2];
        u32 hh, ll;
        split2h(d0, d1, hh, ll);
        AH[32] = hh;  AL[32] = ll;          // POS(32) = 32
        split2h(d2, 0.f, hh, ll);
        AH[34] = hh;  AL[34] = ll;          // POS(33) = 34
        AH[33] = 0; AL[33] = 0;
        #pragma unroll
        for (int z = 35; z < 40; z++) { AH[z] = 0; AL[z] = 0; }
    }
    __syncthreads();

    const int lane = tid & 31;
    const int warp = tid >> 5;
    const int r = lane >> 2;       // groupID in quad layout
    const int c = lane & 3;        // threadID in group
    const int base = warp * 32;    // this warp's first row

    u64* AHu = (u64*)(smu + OFF_AH);
    u64* ALu = (u64*)(smu + OFF_AL);
    const u64* W0u = (const u64*)(smu + OFF_W0);
    const u64* W1u = (const u64*)(smu + OFF_W1);
    const u64* W2u = (const u64*)(smu + OFF_W2);

    // ===== layers 0 and 1 =====
    layer_n64<5>(AHu, ALu, W0u, smf + OFF_T0, base, r, c);
    layer_n64<4>(AHu, ALu, W1u, smf + OFF_T1, base, r, c);

    // ===== layer 2: K=64, N=128 in two passes; maxpool per 16-row group =====
    float* stage = smf + OFF_STAGE + warp * 256;
    #pragma unroll 1
    for (int p = 0; p < 2; p++) {
        float d[2][8][4];
        #pragma unroll
        for (int m = 0; m < 2; m++)
            #pragma unroll
            for (int j = 0; j < 8; j++)
                { d[m][j][0]=0.f; d[m][j][1]=0.f; d[m][j][2]=0.f; d[m][j][3]=0.f; }
        #pragma unroll
        for (int kt = 0; kt < 4; kt++) {
            u32 ah[2][4], al[2][4];
            load_afrag(ah[0], al[0], AHu, ALu, base + r,      kt, c);
            load_afrag(ah[1], al[1], AHu, ALu, base + 16 + r, kt, c);
            #pragma unroll
            for (int j = 0; j < 8; j++) {
                u64 b = W2u[(64 * p + 8 * j + r) * 20 + kt * 4 + c];
                u32 b0 = lo32(b), b1 = hi32(b);
                #pragma unroll
                for (int m = 0; m < 2; m++) {
                    mma_f16(d[m][j], ah[m][0], ah[m][1], ah[m][2], ah[m][3], b0, b1);
                    mma_f16(d[m][j], al[m][0], al[m][1], al[m][2], al[m][3], b0, b1);
                }
            }
        }
        // maxpool over each 16-row group (rows within m-tile), bias/ReLU after max
        #pragma unroll
        for (int m = 0; m < 2; m++) {
            float mx0[8], mx1[8];
            #pragma unroll
            for (int j = 0; j < 8; j++) {
                mx0[j] = fmaxf(d[m][j][0], d[m][j][2]);
                mx1[j] = fmaxf(d[m][j][1], d[m][j][3]);
            }
            #pragma unroll
            for (int off = 4; off <= 16; off <<= 1) {
                #pragma unroll
                for (int j = 0; j < 8; j++) {
                    mx0[j] = fmaxf(mx0[j], __shfl_xor_sync(0xffffffffu, mx0[j], off));
                    mx1[j] = fmaxf(mx1[j], __shfl_xor_sync(0xffffffffu, mx1[j], off));
                }
            }
            if (lane < 4) {
                #pragma unroll
                for (int j = 0; j < 8; j++) {
                    float2 tv = *(const float2*)(smf + OFF_T2 + 64 * p + 8 * j + 2 * c);
                    float2 o;
                    o.x = fmaxf(mx0[j] + tv.x, 0.f);
                    o.y = fmaxf(mx1[j] + tv.y, 0.f);
                    *(float2*)(stage + m * 128 + 64 * p + 8 * j + 2 * c) = o;
                }
            }
        }
    }
    __syncwarp();

    // ---- coalesced output: 2 groups x 128 floats per warp ----
    #pragma unroll
    for (int m = 0; m < 2; m++) {
        float4 o = ((const float4*)(stage + m * 128))[lane];
        const long ofs = (long)(blockIdx.x * 16 + warp * 2 + m) * 128 + 4 * lane;
        *(float4*)(out + ofs) = o;
        if (copies > 1) *(float4*)(out + OUT_ONE + ofs) = o;
    }
}

extern "C" void kernel_launch(void* const* d_in, const int* in_sizes, int n_in,
                              void* d_out, int out_size)
{
    const float* xyz   = (const float*)d_in[0];
    const float* pts   = (const float*)d_in[1];
    const float* xyzs  = (const float*)d_in[2];
    const int*   nbr   = (const int*)  d_in[3];
    const float* vmask = (const float*)d_in[4];
    const float* w0  = (const float*)d_in[5];
    const float* b0  = (const float*)d_in[6];
    const float* g0  = (const float*)d_in[7];
    const float* be0 = (const float*)d_in[8];
    const float* m0  = (const float*)d_in[9];
    const float* v0  = (const float*)d_in[10];
    const float* w1  = (const float*)d_in[11];
    const float* b1  = (const float*)d_in[12];
    const float* g1  = (const float*)d_in[13];
    const float* be1 = (const float*)d_in[14];
    const float* m1  = (const float*)d_in[15];
    const float* v1  = (const float*)d_in[16];
    const float* w2  = (const float*)d_in[17];
    const float* b2  = (const float*)d_in[18];
    const float* g2  = (const float*)d_in[19];
    const float* be2 = (const float*)d_in[20];
    const float* m2  = (const float*)d_in[21];
    const float* v2  = (const float*)d_in[22];

    int copies = (out_size >= 2 * OUT_ONE) ? 2 : 1;

    cudaFuncSetAttribute(pointnet_sa_hmma2_kernel,
                         cudaFuncAttributeMaxDynamicSharedMemorySize, SMEM_BYTES);

    const int blocks = (4 * NS_SZ) / 16;   // 4096 CTAs x 256 rows
    pointnet_sa_hmma2_kernel<<<blocks, THREADS, SMEM_BYTES>>>(
        xyz, pts, xyzs, nbr, vmask,
        w0, b0, g0, be0, m0, v0,
        w1, b1, g1, be1, m1, v1,
        w2, b2, g2, be2, m2, v2,
        (float*)d_out, copies);
}

// round 12
// speedup vs baseline: 2.0567x; 1.2699x over previous
#include <cuda_runtime.h>
#include <cuda_fp16.h>
#include <cstdint>

// PointNetSaModule via mma.sync fp16 2-term split (sm_103-safe HMMA).
// A = ah + al (fp16 split); W = single fp16. D = ah@W + al@W in f32.
// R11: 512 threads / 16 warps / 512 rows per CTA (occupancy 2x vs R10),
// warp = 32 rows (M=32 keeps B-load amortization). Max over 16-row groups.

typedef uint32_t u32;
typedef uint64_t u64;

#define NS_SZ  16384
#define HW_SZ  65536
#define OUT_ONE (4 * 16384 * 128)
#define THREADS 512
#define WARPS   16
#define ROWS    512

// u32 offsets in dynamic smem
#define OFF_T0    0
#define OFF_T1    64
#define OFF_T2    128
#define OFF_S0    256
#define OFF_S1    320
#define OFF_S2    384
#define OFF_AH    512                     // 512 rows x 40 u32
#define OFF_AL    (OFF_AH + ROWS * 40)    // 21012...: 512+20480 = 20992
#define OFF_W0    (OFF_AL + ROWS * 40)    // 41472  (64 x 40)
#define OFF_W1    (OFF_W0 + 64 * 40)      // 44032
#define OFF_W2    (OFF_W1 + 64 * 40)      // 46592  (128 x 40)
#define OFF_STAGE (OFF_W2 + 128 * 40)     // 51712  (16 warps x 256 f32)
#define SMEM_U32  (OFF_STAGE + WARPS * 256)   // 55808
#define SMEM_BYTES (SMEM_U32 * 4)             // 223232

// physical slot of logical kpair p (interleave (c, c+4) adjacent within ktile)
__device__ __forceinline__ int POS(int p) {
    int q = p & 7;
    return (p & ~7) + ((q < 4) ? 2 * q : 2 * (q - 4) + 1);
}

__device__ __forceinline__ u32 packh2(float lo, float hi) {   // low half = lo
    __half2 h = __floats2half2_rn(lo, hi);
    return *(u32*)&h;
}
__device__ __forceinline__ void split2h(float y0, float y1, u32& h, u32& l) {
    h = packh2(y0, y1);
    __half2 hh = *(__half2*)&h;
    float2 f = __half22float2(hh);
    l = packh2(y0 - f.x, y1 - f.y);
}
__device__ __forceinline__ void mma_f16(float* d, u32 a0, u32 a1, u32 a2, u32 a3,
                                        u32 b0, u32 b1) {
    asm("mma.sync.aligned.m16n8k16.row.col.f32.f16.f16.f32 "
        "{%0,%1,%2,%3}, {%4,%5,%6,%7}, {%8,%9}, {%0,%1,%2,%3};"
        : "+f"(d[0]), "+f"(d[1]), "+f"(d[2]), "+f"(d[3])
        : "r"(a0), "r"(a1), "r"(a2), "r"(a3), "r"(b0), "r"(b1));
}
__device__ __forceinline__ u32 lo32(u64 v) { return (u32)v; }
__device__ __forceinline__ u32 hi32(u64 v) { return (u32)(v >> 32); }

__device__ __forceinline__ void load_afrag(u32 ah[4], u32 al[4],
        const u64* AHu, const u64* ALu, int rowA, int kt, int c)
{
    u64 v0 = AHu[rowA * 20 + kt * 4 + c];
    u64 v1 = AHu[(rowA + 8) * 20 + kt * 4 + c];
    ah[0] = lo32(v0); ah[2] = hi32(v0);
    ah[1] = lo32(v1); ah[3] = hi32(v1);
    u64 w0 = ALu[rowA * 20 + kt * 4 + c];
    u64 w1 = ALu[(rowA + 8) * 20 + kt * 4 + c];
    al[0] = lo32(w0); al[2] = hi32(w0);
    al[1] = lo32(w1); al[3] = hi32(w1);
}

__device__ __forceinline__ void epi_store(float d[][4], u64* AHu, u64* ALu,
        const float* T, int rowA, int c)
{
    #pragma unroll
    for (int t = 0; t < 4; t++) {
        float2 tA = *(const float2*)(T + 16 * t + 2 * c);
        float2 tB = *(const float2*)(T + 16 * t + 8 + 2 * c);
        {
            float y00 = fmaxf(d[2*t][0]   + tA.x, 0.f), y01 = fmaxf(d[2*t][1]   + tA.y, 0.f);
            float y10 = fmaxf(d[2*t+1][0] + tB.x, 0.f), y11 = fmaxf(d[2*t+1][1] + tB.y, 0.f);
            u32 hA, lA, hB, lB;
            split2h(y00, y01, hA, lA); split2h(y10, y11, hB, lB);
            AHu[rowA * 20 + 4 * t + c] = (u64)hA | ((u64)hB << 32);
            ALu[rowA * 20 + 4 * t + c] = (u64)lA | ((u64)lB << 32);
        }
        {
            float y00 = fmaxf(d[2*t][2]   + tA.x, 0.f), y01 = fmaxf(d[2*t][3]   + tA.y, 0.f);
            float y10 = fmaxf(d[2*t+1][2] + tB.x, 0.f), y11 = fmaxf(d[2*t+1][3] + tB.y, 0.f);
            u32 hA, lA, hB, lB;
            split2h(y00, y01, hA, lA); split2h(y10, y11, hB, lB);
            AHu[(rowA + 8) * 20 + 4 * t + c] = (u64)hA | ((u64)hB << 32);
            ALu[(rowA + 8) * 20 + 4 * t + c] = (u64)lA | ((u64)lB << 32);
        }
    }
}

template<int NKT>
__device__ __forceinline__ void layer_n64(u64* AHu, u64* ALu, const u64* Wu,
        const float* T, int base, int r, int c)
{
    float d[2][8][4];
    #pragma unroll
    for (int m = 0; m < 2; m++)
        #pragma unroll
        for (int j = 0; j < 8; j++)
            { d[m][j][0]=0.f; d[m][j][1]=0.f; d[m][j][2]=0.f; d[m][j][3]=0.f; }
    #pragma unroll
    for (int kt = 0; kt < NKT; kt++) {
        u32 ah[2][4], al[2][4];
        load_afrag(ah[0], al[0], AHu, ALu, base + r,      kt, c);
        load_afrag(ah[1], al[1], AHu, ALu, base + 16 + r, kt, c);
        #pragma unroll
        for (int j = 0; j < 8; j++) {
            u64 b = Wu[(8 * j + r) * 20 + kt * 4 + c];
            u32 b0 = lo32(b), b1 = hi32(b);
            #pragma unroll
            for (int m = 0; m < 2; m++) {
                mma_f16(d[m][j], ah[m][0], ah[m][1], ah[m][2], ah[m][3], b0, b1);
                mma_f16(d[m][j], al[m][0], al[m][1], al[m][2], al[m][3], b0, b1);
            }
        }
    }
    __syncwarp();
    epi_store(d[0], AHu, ALu, T, base + r,      c);
    epi_store(d[1], AHu, ALu, T, base + 16 + r, c);
    __syncwarp();
}

__global__ void __launch_bounds__(THREADS, 1)
pointnet_sa_hmma3_kernel(
    const float* __restrict__ xyz, const float* __restrict__ pts,
    const float* __restrict__ xyzs, const int* __restrict__ nbr,
    const float* __restrict__ vmask,
    const float* __restrict__ w0, const float* __restrict__ b0,
    const float* __restrict__ g0, const float* __restrict__ be0,
    const float* __restrict__ m0, const float* __restrict__ v0,
    const float* __restrict__ w1, const float* __restrict__ b1,
    const float* __restrict__ g1, const float* __restrict__ be1,
    const float* __restrict__ m1, const float* __restrict__ v1,
    const float* __restrict__ w2, const float* __restrict__ b2,
    const float* __restrict__ g2, const float* __restrict__ be2,
    const float* __restrict__ m2, const float* __restrict__ v2,
    float* __restrict__ out, int copies)
{
    extern __shared__ u32 smu[];
    float* smf = (float*)smu;
    const int tid = threadIdx.x;

    // ---- BN fold scales + biases ----
    if (tid < 64) {
        float s = g0[tid] * rsqrtf(v0[tid] + 1e-5f);
        smf[OFF_S0 + tid] = s;
        smf[OFF_T0 + tid] = (b0[tid] - m0[tid]) * s + be0[tid];
        float s1 = g1[tid] * rsqrtf(v1[tid] + 1e-5f);
        smf[OFF_S1 + tid] = s1;
        smf[OFF_T1 + tid] = (b1[tid] - m1[tid]) * s1 + be1[tid];
    }
    if (tid < 128) {
        float s = g2[tid] * rsqrtf(v2[tid] + 1e-5f);
        smf[OFF_S2 + tid] = s;
        smf[OFF_T2 + tid] = (b2[tid] - m2[tid]) * s + be2[tid];
    }
    __syncthreads();

    // ---- weight tiles (single fp16, [n][kpair phys], stride 40) ----
    for (int i = tid; i < 64 * 40; i += THREADS) {
        int n = i / 40, pos = i % 40;
        int q = pos & 7;
        int p = (pos & ~7) + ((q & 1) ? (q >> 1) + 4 : (q >> 1));
        int k0 = 2 * p, k1 = k0 + 1;
        float s = smf[OFF_S0 + n];
        float a = 0.f, b = 0.f;
        if (k0 < 67) { int sr = (k0 < 64) ? k0 + 3 : k0 - 64; a = w0[sr * 64 + n] * s; }
        if (k1 < 67) { int sr = (k1 < 64) ? k1 + 3 : k1 - 64; b = w0[sr * 64 + n] * s; }
        smu[OFF_W0 + i] = packh2(a, b);
    }
    for (int i = tid; i < 64 * 40; i += THREADS) {
        int n = i / 40, pos = i % 40;
        int q = pos & 7;
        int p = (pos & ~7) + ((q & 1) ? (q >> 1) + 4 : (q >> 1));
        int k0 = 2 * p;
        float s = smf[OFF_S1 + n];
        float a = (k0 < 64)     ? w1[k0 * 64 + n] * s       : 0.f;
        float b = (k0 + 1 < 64) ? w1[(k0 + 1) * 64 + n] * s : 0.f;
        smu[OFF_W1 + i] = packh2(a, b);
    }
    for (int i = tid; i < 128 * 40; i += THREADS) {
        int n = i / 40, pos = i % 40;
        int q = pos & 7;
        int p = (pos & ~7) + ((q & 1) ? (q >> 1) + 4 : (q >> 1));
        int k0 = 2 * p;
        float s = smf[OFF_S2 + n];
        float a = (k0 < 64)     ? w2[k0 * 128 + n] * s       : 0.f;
        float b = (k0 + 1 < 64) ? w2[(k0 + 1) * 128 + n] * s : 0.f;
        smu[OFF_W2 + i] = packh2(a, b);
    }

    // ---- gather: thread owns row = tid (512 rows/CTA) ----
    {
        const int r = tid;
        const int grp = blockIdx.x * 32 + (r >> 4);
        const int b = grp >> 14, n = grp & (NS_SZ - 1);
        const int e = grp * 16 + (r & 15);
        const int idx = nbr[e];
        const float mk = vmask[e];
        const float4* pp = (const float4*)(pts + (size_t)(b * HW_SZ + idx) * 64);
        u32* AH = smu + OFF_AH + r * 40;
        u32* AL = smu + OFF_AL + r * 40;
        #pragma unroll
        for (int i = 0; i < 16; i++) {
            float4 v = pp[i];
            v.x *= mk; v.y *= mk; v.z *= mk; v.w *= mk;
            u32 hh, ll;
            split2h(v.x, v.y, hh, ll);
            AH[POS(2 * i)] = hh;  AL[POS(2 * i)] = ll;
            split2h(v.z, v.w, hh, ll);
            AH[POS(2 * i + 1)] = hh;  AL[POS(2 * i + 1)] = ll;
        }
        const float* cp = xyzs + (size_t)(b * NS_SZ + n) * 3;
        const float* gx = xyz + (size_t)(b * HW_SZ + idx) * 3;
        float d0 = gx[0] * mk - cp[0];
        float d1 = gx[1] * mk - cp[1];
        float d2 = gx[2] * mk - cp[2];
        u32 hh, ll;
        split2h(d0, d1, hh, ll);
        AH[32] = hh;  AL[32] = ll;          // POS(32) = 32
        split2h(d2, 0.f, hh, ll);
        AH[34] = hh;  AL[34] = ll;          // POS(33) = 34
        AH[33] = 0; AL[33] = 0;
        #pragma unroll
        for (int z = 35; z < 40; z++) { AH[z] = 0; AL[z] = 0; }
    }
    __syncthreads();

    const int lane = tid & 31;
    const int warp = tid >> 5;
    const int r = lane >> 2;       // groupID in quad layout
    const int c = lane & 3;        // threadID in group
    const int base = warp * 32;    // this warp's first row

    u64* AHu = (u64*)(smu + OFF_AH);
    u64* ALu = (u64*)(smu + OFF_AL);
    const u64* W0u = (const u64*)(smu + OFF_W0);
    const u64* W1u = (const u64*)(smu + OFF_W1);
    const u64* W2u = (const u64*)(smu + OFF_W2);

    // ===== layers 0 and 1 =====
    layer_n64<5>(AHu, ALu, W0u, smf + OFF_T0, base, r, c);
    layer_n64<4>(AHu, ALu, W1u, smf + OFF_T1, base, r, c);

    // ===== layer 2: K=64, N=128 in two passes; maxpool per 16-row group =====
    float* stage = smf + OFF_STAGE + warp * 256;
    #pragma unroll 1
    for (int p = 0; p < 2; p++) {
        float d[2][8][4];
        #pragma unroll
        for (int m = 0; m < 2; m++)
            #pragma unroll
            for (int j = 0; j < 8; j++)
                { d[m][j][0]=0.f; d[m][j][1]=0.f; d[m][j][2]=0.f; d[m][j][3]=0.f; }
        #pragma unroll
        for (int kt = 0; kt < 4; kt++) {
            u32 ah[2][4], al[2][4];
            load_afrag(ah[0], al[0], AHu, ALu, base + r,      kt, c);
            load_afrag(ah[1], al[1], AHu, ALu, base + 16 + r, kt, c);
            #pragma unroll
            for (int j = 0; j < 8; j++) {
                u64 b = W2u[(64 * p + 8 * j + r) * 20 + kt * 4 + c];
                u32 b0 = lo32(b), b1 = hi32(b);
                #pragma unroll
                for (int m = 0; m < 2; m++) {
                    mma_f16(d[m][j], ah[m][0], ah[m][1], ah[m][2], ah[m][3], b0, b1);
                    mma_f16(d[m][j], al[m][0], al[m][1], al[m][2], al[m][3], b0, b1);
                }
            }
        }
        #pragma unroll
        for (int m = 0; m < 2; m++) {
            float mx0[8], mx1[8];
            #pragma unroll
            for (int j = 0; j < 8; j++) {
                mx0[j] = fmaxf(d[m][j][0], d[m][j][2]);
                mx1[j] = fmaxf(d[m][j][1], d[m][j][3]);
            }
            #pragma unroll
            for (int off = 4; off <= 16; off <<= 1) {
                #pragma unroll
                for (int j = 0; j < 8; j++) {
                    mx0[j] = fmaxf(mx0[j], __shfl_xor_sync(0xffffffffu, mx0[j], off));
                    mx1[j] = fmaxf(mx1[j], __shfl_xor_sync(0xffffffffu, mx1[j], off));
                }
            }
            if (lane < 4) {
                #pragma unroll
                for (int j = 0; j < 8; j++) {
                    float2 tv = *(const float2*)(smf + OFF_T2 + 64 * p + 8 * j + 2 * c);
                    float2 o;
                    o.x = fmaxf(mx0[j] + tv.x, 0.f);
                    o.y = fmaxf(mx1[j] + tv.y, 0.f);
                    *(float2*)(stage + m * 128 + 64 * p + 8 * j + 2 * c) = o;
                }
            }
        }
    }
    __syncwarp();

    // ---- coalesced output: 2 groups x 128 floats per warp ----
    #pragma unroll
    for (int m = 0; m < 2; m++) {
        float4 o = ((const float4*)(stage + m * 128))[lane];
        const long ofs = (long)(blockIdx.x * 32 + warp * 2 + m) * 128 + 4 * lane;
        *(float4*)(out + ofs) = o;
        if (copies > 1) *(float4*)(out + OUT_ONE + ofs) = o;
    }
}

extern "C" void kernel_launch(void* const* d_in, const int* in_sizes, int n_in,
                              void* d_out, int out_size)
{
    const float* xyz   = (const float*)d_in[0];
    const float* pts   = (const float*)d_in[1];
    const float* xyzs  = (const float*)d_in[2];
    const int*   nbr   = (const int*)  d_in[3];
    const float* vmask = (const float*)d_in[4];
    const float* w0  = (const float*)d_in[5];
    const float* b0  = (const float*)d_in[6];
    const float* g0  = (const float*)d_in[7];
    const float* be0 = (const float*)d_in[8];
    const float* m0  = (const float*)d_in[9];
    const float* v0  = (const float*)d_in[10];
    const float* w1  = (const float*)d_in[11];
    const float* b1  = (const float*)d_in[12];
    const float* g1  = (const float*)d_in[13];
    const float* be1 = (const float*)d_in[14];
    const float* m1  = (const float*)d_in[15];
    const float* v1  = (const float*)d_in[16];
    const float* w2  = (const float*)d_in[17];
    const float* b2  = (const float*)d_in[18];
    const float* g2  = (const float*)d_in[19];
    const float* be2 = (const float*)d_in[20];
    const float* m2  = (const float*)d_in[21];
    const float* v2  = (const float*)d_in[22];

    int copies = (out_size >= 2 * OUT_ONE) ? 2 : 1;

    cudaFuncSetAttribute(pointnet_sa_hmma3_kernel,
                         cudaFuncAttributeMaxDynamicSharedMemorySize, SMEM_BYTES);

    const int blocks = (4 * NS_SZ) / 32;   // 2048 CTAs x 512 rows
    pointnet_sa_hmma3_kernel<<<blocks, THREADS, SMEM_BYTES>>>(
        xyz, pts, xyzs, nbr, vmask,
        w0, b0, g0, be0, m0, v0,
        w1, b1, g1, be1, m1, v1,
        w2, b2, g2, be2, m2, v2,
        (float*)d_out, copies);
}